// round 2
// baseline (speedup 1.0000x reference)
#include <cuda_runtime.h>
#include <cuda_bf16.h>
#include <math.h>

// ---------------- problem constants ----------------
#define BB   4
#define CF   512
#define KC   19
#define NT   1024            // tokens per image (32x32)
#define IMG  512
#define PPX  256             // patch pixels (16x16)

// output layout (floats): sfc, tfc, slc, tlc, s_proto, t_proto
#define SZ_FC    ((size_t)BB*NT*CF)               // 2,097,152
#define OFF_SFC  0ULL
#define OFF_TFC  (SZ_FC)                          // 2,097,152
#define OFF_SLC  (2*SZ_FC)                        // 4,194,304
#define SZ_LC    ((size_t)BB*KC*PPX*NT)           // 19,922,944
#define OFF_TLC  (OFF_SLC + SZ_LC)                // 24,117,248
#define OFF_SP   (OFF_TLC + SZ_LC)                // 44,040,192

// ---------------- device scratch (static; no allocation) ----------------
__device__ float g_stok[BB*NT*CF];                 // [b][n][c]
__device__ float g_ttok[BB*NT*CF];
__device__ int           g_mode[2*BB*NT];          // [t][b][n]
__device__ unsigned char g_pure[2*BB*NT];
__device__ float g_proto[2*KC*CF];                 // chained over b
__device__ int   g_clist[2*KC*NT];                 // current b: per-class token lists
__device__ int   g_ccnt [2*KC];
__device__ int   g_rank [2*NT];                    // current b: member rank within class
__device__ int   g_implist[2*NT];
__device__ int   g_impcnt[2];
__device__ int   g_gate[2];
__device__ float g_dist [2*NT];
__device__ int   g_order[2*KC*NT];                 // current b: dist-sorted members
__device__ int           g_src  [2*BB*NT];         // persisted per b
__device__ unsigned char g_apply[2*BB*NT];
__device__ float g_statmean[BB*2*CF];
__device__ float g_statstd [BB*2*CF];
__device__ int   g_both[BB];

// ---------------- kernels ----------------

__global__ void k_zero_proto() {
    int i = blockIdx.x * 1024 + threadIdx.x;
    if (i < 2*KC*CF) g_proto[i] = 0.f;
}

// bilinear 2x upsample (jax.image.resize semantics; edge-renorm == clamp here)
// grid (32 yo, B, 2 tensor), block 512 = channel
__global__ void k_upsample(const float* __restrict__ sfeat, const float* __restrict__ tfeat) {
    int yo = blockIdx.x, b = blockIdx.y, t = blockIdx.z;
    int c = threadIdx.x;
    const float* in = t ? tfeat : sfeat;
    float* dst = t ? g_ttok : g_stok;
    int k = yo >> 1; int r0, r1; float wy0, wy1;
    if (yo & 1) { r0 = k; r1 = (k < 15) ? k + 1 : 15; wy0 = 0.75f; wy1 = 0.25f; }
    else        { r0 = (k > 0) ? k - 1 : 0; r1 = k;   wy0 = 0.25f; wy1 = 0.75f; }
    const float* base = in + ((size_t)b * CF + c) * 256;
    float a0[16], a1[16];
#pragma unroll
    for (int x = 0; x < 16; x++) { a0[x] = base[r0*16 + x]; a1[x] = base[r1*16 + x]; }
#pragma unroll
    for (int xo = 0; xo < 32; xo++) {
        int kx = xo >> 1; int x0, x1; float wx0, wx1;
        if (xo & 1) { x0 = kx; x1 = (kx < 15) ? kx + 1 : 15; wx0 = 0.75f; wx1 = 0.25f; }
        else        { x0 = (kx > 0) ? kx - 1 : 0; x1 = kx;   wx0 = 0.25f; wx1 = 0.75f; }
        float v0 = wy0 * a0[x0] + wy1 * a1[x0];
        float v1 = wy0 * a0[x1] + wy1 * a1[x1];
        dst[((size_t)b * NT + yo*32 + xo) * CF + c] = wx0 * v0 + wx1 * v1;
    }
}

// grid (NT, B), block 256: source patch mode/purity
__global__ void k_patch_s(const int* __restrict__ slab) {
    int n = blockIdx.x, b = blockIdx.y, tid = threadIdx.x;
    int pi = tid >> 4, pj = tid & 15;
    int y = (n >> 5) * 16 + pi, x = (n & 31) * 16 + pj;
    int lab = slab[((size_t)b * IMG + y) * IMG + x];
    __shared__ int h[20];
    if (tid < 20) h[tid] = 0;
    __syncthreads();
    atomicAdd(&h[lab + 1], 1);
    __syncthreads();
    if (tid == 0) {
        int best = -1, mj = 0;
        for (int j = 0; j < 20; j++) if (h[j] > best) { best = h[j]; mj = j; }
        int mode = mj - 1;
        int nvalid = 256 - h[0];
        int agree = (mode >= 0) ? h[mj] : 0;
        float purity = (float)agree / (float)(nvalid > 0 ? nvalid : 1);
        g_mode[b * NT + n] = mode;
        g_pure[b * NT + n] = (unsigned char)((purity >= 0.9f) && (nvalid > 0));
    }
}

// grid (NT, B), block 256: target conf/argmax, patch mode/purity + conf gate
__global__ void k_patch_t(const float* __restrict__ tp) {
    int n = blockIdx.x, b = blockIdx.y, tid = threadIdx.x;
    int pi = tid >> 4, pj = tid & 15;
    int y = (n >> 5) * 16 + pi, x = (n & 31) * 16 + pj;
    size_t pix = ((size_t)b * KC * IMG + y) * IMG + x;
    float mv = -1.f; int mk = 0;
#pragma unroll
    for (int k = 0; k < KC; k++) {
        float p = tp[pix + (size_t)k * (IMG * IMG)];
        if (p > mv) { mv = p; mk = k; }
    }
    int lab = (mv < 0.9f) ? -1 : mk;
    __shared__ int h[20];
    __shared__ float sc[256];
    if (tid < 20) h[tid] = 0;
    sc[tid] = mv;
    __syncthreads();
    atomicAdd(&h[lab + 1], 1);
    __syncthreads();
    for (int s = 128; s > 0; s >>= 1) {
        if (tid < s) sc[tid] += sc[tid + s];
        __syncthreads();
    }
    if (tid == 0) {
        float cmean = sc[0] / 256.f;
        int best = -1, mj = 0;
        for (int j = 0; j < 20; j++) if (h[j] > best) { best = h[j]; mj = j; }
        int mode = mj - 1;
        int nvalid = 256 - h[0];
        int agree = (mode >= 0) ? h[mj] : 0;
        float purity = (float)agree / (float)(nvalid > 0 ? nvalid : 1);
        int pure = (purity >= 0.9f) && (nvalid > 0) && (cmean >= 0.9f);
        g_mode[BB*NT + b * NT + n] = mode;
        g_pure[BB*NT + b * NT + n] = (unsigned char)pure;
    }
}

// per-b: compact class lists, ranks, impure lists, gates. 1 block, 1024 threads.
__global__ void k_prep(int b) {
    int tid = threadIdx.x, w = tid >> 5, lane = tid & 31;
    for (int item = w; item < 40; item += 32) {
        if (item < 38) {
            int t = item / KC, k = item % KC;
            const int* md = g_mode + t * BB * NT + b * NT;
            const unsigned char* pu = g_pure + t * BB * NT + b * NT;
            int cnt = 0;
            for (int base = 0; base < NT; base += 32) {
                int n = base + lane;
                bool mem = pu[n] && (md[n] == k);
                unsigned m = __ballot_sync(0xffffffffu, mem);
                int pos = cnt + __popc(m & ((1u << lane) - 1u));
                if (mem) { g_clist[(t * KC + k) * NT + pos] = n; g_rank[t * NT + n] = pos; }
                cnt += __popc(m);
            }
            if (lane == 0) g_ccnt[t * KC + k] = cnt;
        } else {
            int t = item - 38;
            const unsigned char* pu = g_pure + t * BB * NT + b * NT;
            int cnt = 0;
            for (int base = 0; base < NT; base += 32) {
                int n = base + lane;
                bool mem = !pu[n];
                unsigned m = __ballot_sync(0xffffffffu, mem);
                int pos = cnt + __popc(m & ((1u << lane) - 1u));
                if (mem) g_implist[t * NT + pos] = n;
                cnt += __popc(m);
            }
            if (lane == 0) g_impcnt[t] = cnt;
        }
    }
    __syncthreads();
    if (tid < 2) {
        int s = 0;
        for (int k = 0; k < KC; k++) s += g_ccnt[tid * KC + k];
        g_gate[tid] = (s > 0);
    }
}

// per-b: class means + fused momentum prototype update. grid 38, block 512.
__global__ void k_accum(int b) {
    int bid = blockIdx.x;          // t*19+k
    int t = bid / KC, c = threadIdx.x;
    int cnt = g_ccnt[bid];
    __shared__ int lst[NT];
    for (int i = c; i < cnt; i += 512) lst[i] = g_clist[bid * NT + i];
    __syncthreads();
    const float* feat = (t ? g_ttok : g_stok) + (size_t)b * NT * CF;
    float acc = 0.f;
    for (int i = 0; i < cnt; i++) acc += feat[(size_t)lst[i] * CF + c];
    int gate_ok = t ? (g_gate[0] && g_gate[1]) : g_gate[0];
    if (gate_ok && cnt > 0) {
        float mean = acc / (float)cnt;
        float* pp = g_proto + bid * CF + c;
        *pp = 0.99f * (*pp) + 0.01f * mean;
    }
}

// per-b: impure-token channel mean/std (two-pass, unbiased). grid 2, block 512.
__global__ void k_stats(int b) {
    int t = blockIdx.x, c = threadIdx.x;
    int n = g_impcnt[t];
    __shared__ int lst[NT];
    for (int i = c; i < n; i += 512) lst[i] = g_implist[t * NT + i];
    __syncthreads();
    const float* feat = (t ? g_ttok : g_stok) + (size_t)b * NT * CF;
    float s = 0.f;
    for (int i = 0; i < n; i++) s += feat[(size_t)lst[i] * CF + c];
    float mean = s / (float)(n > 0 ? n : 1);
    float ss = 0.f;
    for (int i = 0; i < n; i++) { float d = feat[(size_t)lst[i] * CF + c] - mean; ss += d * d; }
    float var = ss / (float)(n - 1 > 0 ? n - 1 : 1);
    float sd = (n > 1) ? sqrtf(var) : 0.f;
    g_statmean[(b * 2 + t) * CF + c] = mean;
    g_statstd [(b * 2 + t) * CF + c] = sd;
    if (t == 0 && c == 0) g_both[b] = (g_impcnt[0] > 0) && (g_impcnt[1] > 0);
}

// per-b: distance to own-class prototype. grid (64, 2), block 512 (16 warps).
__global__ void k_dist(int b) {
    int t = blockIdx.y;
    int w = threadIdx.x >> 5, lane = threadIdx.x & 31;
    int n = blockIdx.x * 16 + w;
    int mode = g_mode[t * BB * NT + b * NT + n];
    int cm = mode > 0 ? mode : 0;
    const float* f = (t ? g_ttok : g_stok) + ((size_t)b * NT + n) * CF;
    const float* p = g_proto + (t * KC + cm) * CF;
    float acc = 0.f;
    for (int c = lane; c < CF; c += 32) { float d = f[c] - p[c]; acc += d * d; }
    for (int o = 16; o; o >>= 1) acc += __shfl_down_sync(0xffffffffu, acc, o);
    if (lane == 0) g_dist[t * NT + n] = sqrtf(acc);
}

// per-b: stable sort members by distance (rank via counting). grid (19,2), block 256.
__global__ void k_sort() {
    int k = blockIdx.x, t = blockIdx.y, bid = t * KC + k;
    int m = g_ccnt[bid];
    __shared__ int toks[NT];
    __shared__ float ds[NT];
    for (int i = threadIdx.x; i < m; i += 256) {
        int tk = g_clist[bid * NT + i];
        toks[i] = tk; ds[i] = g_dist[t * NT + tk];
    }
    __syncthreads();
    for (int i = threadIdx.x; i < m; i += 256) {
        float di = ds[i]; int r = 0;
        for (int j = 0; j < m; j++) {
            float dj = ds[j];
            r += (dj < di) || (dj == di && j < i);
        }
        g_order[bid * NT + r] = toks[i];
    }
}

// per-b: cyclic source matching. grid 2, block 1024.
__global__ void k_match(int b) {
    int t = blockIdx.x, n = threadIdx.x;
    int gate_st = g_gate[0] && g_gate[1];
    int mode = g_mode[t * BB * NT + b * NT + n];
    int pure = g_pure[t * BB * NT + b * NT + n];
    int c = mode > 0 ? mode : 0;
    int cs = g_ccnt[(1 - t) * KC + c];
    int apply = pure && (cs > 0) && gate_st;
    int src = 0;
    if (apply) {
        int r = g_rank[t * NT + n];
        src = g_order[((1 - t) * KC + c) * NT + (r % cs)];
    }
    g_src  [(t * BB + b) * NT + n] = src;
    g_apply[(t * BB + b) * NT + n] = (unsigned char)apply;
}

// batched feature correction. grid (NT, 2, B), block 512.
__global__ void k_featcorr(const float* __restrict__ alphas, float* __restrict__ out) {
    int n = blockIdx.x, t = blockIdx.y, b = blockIdx.z, c = threadIdx.x;
    float alpha = alphas[b];
    const float* own = (t ? g_ttok : g_stok) + (size_t)b * NT * CF;
    const float* oth = (t ? g_stok : g_ttok) + (size_t)b * NT * CF;
    float f = own[(size_t)n * CF + c];
    float r = f;
    int idx = (t * BB + b) * NT + n;
    if (g_apply[idx]) {
        r = alpha * f + (1.f - alpha) * oth[(size_t)g_src[idx] * CF + c];
    } else if (!g_pure[t * BB * NT + b * NT + n] && g_both[b]) {
        float om = g_statmean[(b * 2 + t) * CF + c];
        float os = g_statstd [(b * 2 + t) * CF + c];
        float xm = g_statmean[(b * 2 + (1 - t)) * CF + c];
        float xs = g_statstd [(b * 2 + (1 - t)) * CF + c];
        float styl = (f - om) / (os + 1e-5f) * xs + xm;
        r = alpha * f + (1.f - alpha) * styl;
    }
    out[(t ? OFF_TFC : OFF_SFC) + ((size_t)b * NT + n) * CF + c] = r;
}

// batched label correction (the big writes). grid (8 chunks, K*16, B*2), block 256.
__global__ void k_labelcorr(const int* __restrict__ slab, const float* __restrict__ tp,
                            float* __restrict__ out) {
    int chunk = blockIdx.x;
    int k = blockIdx.y >> 4, pi = blockIdx.y & 15;
    int b = blockIdx.z >> 1, osel = blockIdx.z & 1;   // 0=slc, 1=tlc
    int tid = threadIdx.x;
    __shared__ float seg[128][17];
    int tsel = osel;                                   // slc->apply_s(t=0), tlc->apply_t(t=1)
    int sseg = tid >> 4, pj = tid & 15;
    for (int pass = 0; pass < 8; pass++) {
        int s = pass * 16 + sseg;
        int n = chunk * 128 + s;
        int aidx = (tsel * BB + b) * NT + n;
        int apply = g_apply[aidx];
        int m = apply ? g_src[aidx] : n;
        int use_probs = (osel == 0) ? apply : !apply;
        int y = (m >> 5) * 16 + pi, x = (m & 31) * 16 + pj;
        float v;
        if (use_probs) v = tp[(((size_t)b * KC + k) * IMG + y) * IMG + x];
        else v = (slab[((size_t)b * IMG + y) * IMG + x] == k) ? 1.f : 0.f;
        seg[s][pj] = v;
    }
    __syncthreads();
    size_t obase = osel ? OFF_TLC : OFF_SLC;
    int nn = tid & 127, pq = tid >> 7;
    for (int pp = 0; pp < 16; pp += 2) {
        int pjw = pp + pq;
        size_t row = (size_t)b * (KC * PPX) + k * PPX + pi * 16 + pjw;
        out[obase + row * NT + chunk * 128 + nn] = seg[nn][pjw];
    }
}

__global__ void k_proto_out(float* __restrict__ out) {
    int i = blockIdx.x * 512 + threadIdx.x;     // 2*19*512 = 19456
    out[OFF_SP + i] = g_proto[i];
}

// ---------------- launch ----------------
extern "C" void kernel_launch(void* const* d_in, const int* in_sizes, int n_in,
                              void* d_out, int out_size) {
    // robust input identification by size, positional for the two feature maps
    const float* sfeat = nullptr; const float* tfeat = nullptr;
    const int* slab = nullptr; const float* tp = nullptr; const float* alphas = nullptr;
    for (int i = 0; i < n_in; i++) {
        int sz = in_sizes[i];
        if (sz == BB*CF*16*16) { if (!sfeat) sfeat = (const float*)d_in[i]; else tfeat = (const float*)d_in[i]; }
        else if (sz == BB*IMG*IMG) slab = (const int*)d_in[i];
        else if (sz == BB*KC*IMG*IMG) tp = (const float*)d_in[i];
        else if (sz == BB) alphas = (const float*)d_in[i];
    }
    float* out = (float*)d_out;

    k_zero_proto<<<19, 1024>>>();
    k_upsample<<<dim3(32, BB, 2), 512>>>(sfeat, tfeat);
    k_patch_s<<<dim3(NT, BB), 256>>>(slab);
    k_patch_t<<<dim3(NT, BB), 256>>>(tp);
    for (int b = 0; b < BB; b++) {
        k_prep<<<1, 1024>>>(b);
        k_accum<<<2 * KC, 512>>>(b);
        k_stats<<<2, 512>>>(b);
        k_dist<<<dim3(64, 2), 512>>>(b);
        k_sort<<<dim3(KC, 2), 256>>>();
        k_match<<<2, 1024>>>(b);
    }
    k_featcorr<<<dim3(NT, 2, BB), 512>>>(alphas, out);
    k_labelcorr<<<dim3(8, KC * 16, BB * 2), 256>>>(slab, tp, out);
    k_proto_out<<<2 * KC, 512>>>(out);
}

// round 3
// speedup vs baseline: 1.4032x; 1.4032x over previous
#include <cuda_runtime.h>
#include <cuda_bf16.h>
#include <math.h>

// ---------------- problem constants ----------------
#define BB   4
#define CF   512
#define KC   19
#define NT   1024            // tokens per image (32x32)
#define IMG  512
#define PPX  256             // patch pixels (16x16)
#define NBLK 38              // chain kernel blocks (2*KC)

// output layout (floats): sfc, tfc, slc, tlc, s_proto, t_proto
#define SZ_FC    ((size_t)BB*NT*CF)
#define OFF_SFC  0ULL
#define OFF_TFC  (SZ_FC)
#define OFF_SLC  (2*SZ_FC)
#define SZ_LC    ((size_t)BB*KC*PPX*NT)
#define OFF_TLC  (OFF_SLC + SZ_LC)
#define OFF_SP   (OFF_TLC + SZ_LC)

// ---------------- device scratch (static; no allocation) ----------------
__device__ float g_stok[BB*NT*CF];                 // [b][n][c]
__device__ float g_ttok[BB*NT*CF];
__device__ int           g_mode[2*BB*NT];          // [t][b][n]
__device__ unsigned char g_pure[2*BB*NT];
__device__ float g_proto[2*KC*CF];                 // chained over b
__device__ int   g_clist[BB*2*KC*NT];              // per-b per-class token lists
__device__ int   g_ccnt [BB*2*KC];
__device__ int   g_rank [BB*2*NT];
__device__ int   g_implist[BB*2*NT];
__device__ int   g_impcnt[BB*2];
__device__ int   g_gate[BB*2];
__device__ int   g_order[2*KC*NT];                 // transient per-b (inside chain)
__device__ int           g_src  [2*BB*NT];
__device__ unsigned char g_apply[2*BB*NT];
__device__ float g_statmean[BB*2*CF];
__device__ float g_statstd [BB*2*CF];
__device__ int   g_both[BB];

// software grid barrier state
__device__ unsigned g_barGen = 0;
__device__ unsigned g_barCnt = 0;

__device__ __forceinline__ void grid_bar() {
    __threadfence();
    __syncthreads();
    if (threadIdx.x == 0) {
        unsigned my = *((volatile unsigned*)&g_barGen);
        unsigned a = atomicAdd(&g_barCnt, 1u);
        if (a == NBLK - 1) {
            atomicExch(&g_barCnt, 0u);
            __threadfence();
            atomicExch(&g_barGen, my + 1u);
        } else {
            while (*((volatile unsigned*)&g_barGen) == my) { __nanosleep(64); }
        }
        __threadfence();
    }
    __syncthreads();
}

// ---------------- kernels ----------------

__global__ void k_zero_proto() {
    int i = blockIdx.x * 1024 + threadIdx.x;
    if (i < 2*KC*CF) g_proto[i] = 0.f;
}

// bilinear 2x upsample; grid (32 yo, B, 2 tensor), block 512 = channel
__global__ void k_upsample(const float* __restrict__ sfeat, const float* __restrict__ tfeat) {
    int yo = blockIdx.x, b = blockIdx.y, t = blockIdx.z;
    int c = threadIdx.x;
    const float* in = t ? tfeat : sfeat;
    float* dst = t ? g_ttok : g_stok;
    int k = yo >> 1; int r0, r1; float wy0, wy1;
    if (yo & 1) { r0 = k; r1 = (k < 15) ? k + 1 : 15; wy0 = 0.75f; wy1 = 0.25f; }
    else        { r0 = (k > 0) ? k - 1 : 0; r1 = k;   wy0 = 0.25f; wy1 = 0.75f; }
    const float* base = in + ((size_t)b * CF + c) * 256;
    float a0[16], a1[16];
#pragma unroll
    for (int x = 0; x < 16; x++) { a0[x] = base[r0*16 + x]; a1[x] = base[r1*16 + x]; }
#pragma unroll
    for (int xo = 0; xo < 32; xo++) {
        int kx = xo >> 1; int x0, x1; float wx0, wx1;
        if (xo & 1) { x0 = kx; x1 = (kx < 15) ? kx + 1 : 15; wx0 = 0.75f; wx1 = 0.25f; }
        else        { x0 = (kx > 0) ? kx - 1 : 0; x1 = kx;   wx0 = 0.25f; wx1 = 0.75f; }
        float v0 = wy0 * a0[x0] + wy1 * a1[x0];
        float v1 = wy0 * a0[x1] + wy1 * a1[x1];
        dst[((size_t)b * NT + yo*32 + xo) * CF + c] = wx0 * v0 + wx1 * v1;
    }
}

// grid (NT, B), block 256: source patch mode/purity
__global__ void k_patch_s(const int* __restrict__ slab) {
    int n = blockIdx.x, b = blockIdx.y, tid = threadIdx.x;
    int pi = tid >> 4, pj = tid & 15;
    int y = (n >> 5) * 16 + pi, x = (n & 31) * 16 + pj;
    int lab = slab[((size_t)b * IMG + y) * IMG + x];
    __shared__ int h[20];
    if (tid < 20) h[tid] = 0;
    __syncthreads();
    atomicAdd(&h[lab + 1], 1);
    __syncthreads();
    if (tid == 0) {
        int best = -1, mj = 0;
        for (int j = 0; j < 20; j++) if (h[j] > best) { best = h[j]; mj = j; }
        int mode = mj - 1;
        int nvalid = 256 - h[0];
        int agree = (mode >= 0) ? h[mj] : 0;
        float purity = (float)agree / (float)(nvalid > 0 ? nvalid : 1);
        g_mode[b * NT + n] = mode;
        g_pure[b * NT + n] = (unsigned char)((purity >= 0.9f) && (nvalid > 0));
    }
}

// grid (NT/4, B), block 256: 4 patches per block, float4 loads (4 px/thread)
__global__ void k_patch_t(const float* __restrict__ tp) {
    int b = blockIdx.y, tid = threadIdx.x;
    int p = tid >> 6, r = tid & 63;
    int pi = r >> 2, xq = r & 3;
    int n = blockIdx.x * 4 + p;
    int y = (n >> 5) * 16 + pi;
    int xbase = (n & 31) * 16 + xq * 4;
    const float4* tp4 = (const float4*)tp;
    size_t pix4 = (((size_t)b * KC) * IMG + y) * (IMG/4) + (xbase >> 2);
    float mv0=-1.f, mv1=-1.f, mv2=-1.f, mv3=-1.f;
    int mk0=0, mk1=0, mk2=0, mk3=0;
#pragma unroll
    for (int k = 0; k < KC; k++) {
        float4 v = tp4[pix4 + (size_t)k * (IMG * (IMG/4))];
        if (v.x > mv0) { mv0 = v.x; mk0 = k; }
        if (v.y > mv1) { mv1 = v.y; mk1 = k; }
        if (v.z > mv2) { mv2 = v.z; mk2 = k; }
        if (v.w > mv3) { mv3 = v.w; mk3 = k; }
    }
    __shared__ int h[4][20];
    __shared__ float sc[256];
    if (tid < 80) h[tid / 20][tid % 20] = 0;
    sc[tid] = mv0 + mv1 + mv2 + mv3;
    __syncthreads();
    int l0 = (mv0 < 0.9f) ? 0 : mk0 + 1;
    int l1 = (mv1 < 0.9f) ? 0 : mk1 + 1;
    int l2 = (mv2 < 0.9f) ? 0 : mk2 + 1;
    int l3 = (mv3 < 0.9f) ? 0 : mk3 + 1;
    atomicAdd(&h[p][l0], 1); atomicAdd(&h[p][l1], 1);
    atomicAdd(&h[p][l2], 1); atomicAdd(&h[p][l3], 1);
    __syncthreads();
    for (int s = 32; s > 0; s >>= 1) {
        if (r < s) sc[tid] += sc[tid + s];
        __syncthreads();
    }
    if (r == 0) {
        float cmean = sc[p * 64] / 256.f;
        int best = -1, mj = 0;
        for (int j = 0; j < 20; j++) if (h[p][j] > best) { best = h[p][j]; mj = j; }
        int mode = mj - 1;
        int nvalid = 256 - h[p][0];
        int agree = (mode >= 0) ? h[p][mj] : 0;
        float purity = (float)agree / (float)(nvalid > 0 ? nvalid : 1);
        int pure = (purity >= 0.9f) && (nvalid > 0) && (cmean >= 0.9f);
        g_mode[BB*NT + b * NT + n] = mode;
        g_pure[BB*NT + b * NT + n] = (unsigned char)pure;
    }
}

// batched: compact class lists, ranks, impure lists, gates. grid (B), 1024 thr.
__global__ void k_prep() {
    int b = blockIdx.x;
    int tid = threadIdx.x, w = tid >> 5, lane = tid & 31;
    for (int item = w; item < 40; item += 32) {
        if (item < 38) {
            int t = item / KC, k = item % KC;
            const int* md = g_mode + t * BB * NT + b * NT;
            const unsigned char* pu = g_pure + t * BB * NT + b * NT;
            int cnt = 0;
            for (int base = 0; base < NT; base += 32) {
                int n = base + lane;
                bool mem = pu[n] && (md[n] == k);
                unsigned m = __ballot_sync(0xffffffffu, mem);
                int pos = cnt + __popc(m & ((1u << lane) - 1u));
                if (mem) {
                    g_clist[((b*2+t)*KC + k)*NT + pos] = n;
                    g_rank[(b*2+t)*NT + n] = pos;
                }
                cnt += __popc(m);
            }
            if (lane == 0) g_ccnt[(b*2+t)*KC + k] = cnt;
        } else {
            int t = item - 38;
            const unsigned char* pu = g_pure + t * BB * NT + b * NT;
            int cnt = 0;
            for (int base = 0; base < NT; base += 32) {
                int n = base + lane;
                bool mem = !pu[n];
                unsigned m = __ballot_sync(0xffffffffu, mem);
                int pos = cnt + __popc(m & ((1u << lane) - 1u));
                if (mem) g_implist[(b*2+t)*NT + pos] = n;
                cnt += __popc(m);
            }
            if (lane == 0) g_impcnt[b*2+t] = cnt;
        }
    }
    __syncthreads();
    if (tid < 2) {
        int s = 0;
        for (int k = 0; k < KC; k++) s += g_ccnt[(b*2+tid)*KC + k];
        g_gate[b*2+tid] = (s > 0);
    }
}

// batched impure stats. grid (2, B), block 512.
__global__ void k_stats() {
    int t = blockIdx.x, b = blockIdx.y, c = threadIdx.x;
    int n = g_impcnt[b*2+t];
    __shared__ int lst[NT];
    for (int i = c; i < n; i += 512) lst[i] = g_implist[(b*2+t)*NT + i];
    __syncthreads();
    const float* feat = (t ? g_ttok : g_stok) + (size_t)b * NT * CF;
    float s = 0.f;
    for (int i = 0; i < n; i++) s += feat[(size_t)lst[i] * CF + c];
    float mean = s / (float)(n > 0 ? n : 1);
    float ss = 0.f;
    for (int i = 0; i < n; i++) { float d = feat[(size_t)lst[i] * CF + c] - mean; ss += d * d; }
    float var = ss / (float)(n - 1 > 0 ? n - 1 : 1);
    float sd = (n > 1) ? sqrtf(var) : 0.f;
    g_statmean[(b * 2 + t) * CF + c] = mean;
    g_statstd [(b * 2 + t) * CF + c] = sd;
    if (t == 0 && c == 0) g_both[b] = (g_impcnt[b*2] > 0) && (g_impcnt[b*2+1] > 0);
}

// fused sequential chain: per b: (EMA proto + member dist + stable sort) -> bar
// -> match -> bar. One block per (t, class). 38 blocks x 512 threads.
__global__ void k_chain() {
    __shared__ int   lst[NT];
    __shared__ float ds[NT];
    __shared__ float pr[CF];
    int bid = blockIdx.x;          // t*KC + k
    int t = bid / KC, k = bid % KC;
    int tid = threadIdx.x;
    int w = tid >> 5, lane = tid & 31;
    for (int b = 0; b < BB; b++) {
        // ---- phase A: proto update + member distances + stable sort ----
        int cnt = g_ccnt[(b*2+t)*KC + k];
        for (int i = tid; i < cnt; i += 512) lst[i] = g_clist[((b*2+t)*KC + k)*NT + i];
        __syncthreads();
        const float* feat = (t ? g_ttok : g_stok) + (size_t)b * NT * CF;
        int c = tid;  // 512 == CF
        float acc = 0.f;
        for (int i = 0; i < cnt; i++) acc += feat[(size_t)lst[i] * CF + c];
        int gate_ok = t ? (g_gate[b*2] && g_gate[b*2+1]) : g_gate[b*2];
        float pv = g_proto[bid * CF + c];
        if (gate_ok && cnt > 0) {
            pv = 0.99f * pv + 0.01f * (acc / (float)cnt);
            g_proto[bid * CF + c] = pv;
        }
        pr[c] = pv;
        __syncthreads();
        for (int i = w; i < cnt; i += 16) {
            const float* f = feat + (size_t)lst[i] * CF;
            float a = 0.f;
            for (int cc = lane; cc < CF; cc += 32) { float d = f[cc] - pr[cc]; a += d * d; }
            for (int o = 16; o; o >>= 1) a += __shfl_down_sync(0xffffffffu, a, o);
            if (lane == 0) ds[i] = sqrtf(a);
        }
        __syncthreads();
        for (int i = tid; i < cnt; i += 512) {
            float di = ds[i]; int r = 0;
            for (int j = 0; j < cnt; j++) {
                float dj = ds[j];
                r += (dj < di) || (dj == di && j < i);
            }
            g_order[bid * NT + r] = lst[i];
        }
        grid_bar();
        // ---- phase B: cyclic source matching over all 2*NT tokens ----
        int gate_st = g_gate[b*2] && g_gate[b*2+1];
        int idx = bid * 512 + tid;
        if (idx < 2 * NT) {
            int t2 = idx >> 10, n = idx & (NT - 1);
            int mode = g_mode[t2 * BB * NT + b * NT + n];
            int pure = g_pure[t2 * BB * NT + b * NT + n];
            int cm = mode > 0 ? mode : 0;
            int cs = g_ccnt[(b*2 + (1 - t2)) * KC + cm];
            int apply = pure && (cs > 0) && gate_st;
            int src = 0;
            if (apply) {
                int r = g_rank[(b*2 + t2) * NT + n];
                src = __ldcg(&g_order[((1 - t2) * KC + cm) * NT + (r % cs)]);
            }
            g_src  [(t2 * BB + b) * NT + n] = src;
            g_apply[(t2 * BB + b) * NT + n] = (unsigned char)apply;
        }
        grid_bar();
    }
}

// batched feature correction. grid (NT, 2, B), block 512.
__global__ void k_featcorr(const float* __restrict__ alphas, float* __restrict__ out) {
    int n = blockIdx.x, t = blockIdx.y, b = blockIdx.z, c = threadIdx.x;
    float alpha = alphas[b];
    const float* own = (t ? g_ttok : g_stok) + (size_t)b * NT * CF;
    const float* oth = (t ? g_stok : g_ttok) + (size_t)b * NT * CF;
    float f = own[(size_t)n * CF + c];
    float r = f;
    int idx = (t * BB + b) * NT + n;
    if (g_apply[idx]) {
        r = alpha * f + (1.f - alpha) * oth[(size_t)g_src[idx] * CF + c];
    } else if (!g_pure[t * BB * NT + b * NT + n] && g_both[b]) {
        float om = g_statmean[(b * 2 + t) * CF + c];
        float os = g_statstd [(b * 2 + t) * CF + c];
        float xm = g_statmean[(b * 2 + (1 - t)) * CF + c];
        float xs = g_statstd [(b * 2 + (1 - t)) * CF + c];
        float styl = (f - om) / (os + 1e-5f) * xs + xm;
        r = alpha * f + (1.f - alpha) * styl;
    }
    out[(t ? OFF_TFC : OFF_SFC) + ((size_t)b * NT + n) * CF + c] = r;
}

// batched label correction. grid (8 chunks, K*16, B*2), block 256.
__global__ void k_labelcorr(const int* __restrict__ slab, const float* __restrict__ tp,
                            float* __restrict__ out) {
    int chunk = blockIdx.x;
    int k = blockIdx.y >> 4, pi = blockIdx.y & 15;
    int b = blockIdx.z >> 1, osel = blockIdx.z & 1;   // 0=slc, 1=tlc
    int tid = threadIdx.x;
    __shared__ float seg[128][17];
    int tsel = osel;
    int sseg = tid >> 4, pj = tid & 15;
    for (int pass = 0; pass < 8; pass++) {
        int s = pass * 16 + sseg;
        int n = chunk * 128 + s;
        int aidx = (tsel * BB + b) * NT + n;
        int apply = g_apply[aidx];
        int m = apply ? g_src[aidx] : n;
        int use_probs = (osel == 0) ? apply : !apply;
        int y = (m >> 5) * 16 + pi, x = (m & 31) * 16 + pj;
        float v;
        if (use_probs) v = tp[(((size_t)b * KC + k) * IMG + y) * IMG + x];
        else v = (slab[((size_t)b * IMG + y) * IMG + x] == k) ? 1.f : 0.f;
        seg[s][pj] = v;
    }
    __syncthreads();
    size_t obase = osel ? OFF_TLC : OFF_SLC;
    int nn = tid & 127, pq = tid >> 7;
    for (int pp = 0; pp < 16; pp += 2) {
        int pjw = pp + pq;
        size_t row = (size_t)b * (KC * PPX) + k * PPX + pi * 16 + pjw;
        out[obase + row * NT + chunk * 128 + nn] = seg[nn][pjw];
    }
}

__global__ void k_proto_out(float* __restrict__ out) {
    int i = blockIdx.x * 512 + threadIdx.x;
    out[OFF_SP + i] = g_proto[i];
}

// ---------------- launch ----------------
extern "C" void kernel_launch(void* const* d_in, const int* in_sizes, int n_in,
                              void* d_out, int out_size) {
    const float* sfeat = nullptr; const float* tfeat = nullptr;
    const int* slab = nullptr; const float* tp = nullptr; const float* alphas = nullptr;
    for (int i = 0; i < n_in; i++) {
        int sz = in_sizes[i];
        if (sz == BB*CF*16*16) { if (!sfeat) sfeat = (const float*)d_in[i]; else tfeat = (const float*)d_in[i]; }
        else if (sz == BB*IMG*IMG) slab = (const int*)d_in[i];
        else if (sz == BB*KC*IMG*IMG) tp = (const float*)d_in[i];
        else if (sz == BB) alphas = (const float*)d_in[i];
    }
    float* out = (float*)d_out;

    k_zero_proto<<<19, 1024>>>();
    k_upsample<<<dim3(32, BB, 2), 512>>>(sfeat, tfeat);
    k_patch_s<<<dim3(NT, BB), 256>>>(slab);
    k_patch_t<<<dim3(NT/4, BB), 256>>>(tp);
    k_prep<<<BB, 1024>>>();
    k_stats<<<dim3(2, BB), 512>>>();
    k_chain<<<NBLK, 512>>>();
    k_featcorr<<<dim3(NT, 2, BB), 512>>>(alphas, out);
    k_labelcorr<<<dim3(8, KC * 16, BB * 2), 256>>>(slab, tp, out);
    k_proto_out<<<2 * KC, 512>>>(out);
}

// round 4
// speedup vs baseline: 1.8075x; 1.2882x over previous
#include <cuda_runtime.h>
#include <cuda_bf16.h>
#include <math.h>

// ---------------- problem constants ----------------
#define BB   4
#define CF   512
#define KC   19
#define NT   1024            // tokens per image (32x32)
#define IMG  512
#define PPX  256             // patch pixels (16x16)
#define TK   (2*KC)          // 38

// output layout (floats): sfc, tfc, slc, tlc, s_proto, t_proto
#define SZ_FC    ((size_t)BB*NT*CF)
#define OFF_SFC  0ULL
#define OFF_TFC  (SZ_FC)
#define OFF_SLC  (2*SZ_FC)
#define SZ_LC    ((size_t)BB*KC*PPX*NT)
#define OFF_TLC  (OFF_SLC + SZ_LC)
#define OFF_SP   (OFF_TLC + SZ_LC)

// ---------------- device scratch (static; no allocation) ----------------
__device__ float g_stok[BB*NT*CF];                 // [b][n][c]
__device__ float g_ttok[BB*NT*CF];
__device__ int           g_mode[2*BB*NT];          // [t][b][n]
__device__ unsigned char g_pure[2*BB*NT];
__device__ int   g_clist[BB*TK*NT];                // [(b*2+t)*KC+k][i]
__device__ int   g_ccnt [BB*TK];
__device__ int   g_rank [BB*2*NT];
__device__ int   g_gate [BB*2];
__device__ float g_mean  [BB*TK*CF];               // per-b class means
__device__ float g_protoB[BB*TK*CF];               // proto state after update b
__device__ float g_proto [TK*CF];                  // final (b=3) state
__device__ float g_dist[BB*2*NT];
__device__ int   g_order[BB*TK*NT];
__device__ int           g_src  [2*BB*NT];
__device__ unsigned char g_apply[2*BB*NT];
__device__ float g_statmean[BB*2*CF];
__device__ float g_statstd [BB*2*CF];
__device__ int   g_both[BB];

// ---------------- kernels ----------------

// bilinear 2x upsample; grid (32 yo, B, 2 tensor), block 512 = channel
__global__ void k_upsample(const float* __restrict__ sfeat, const float* __restrict__ tfeat) {
    int yo = blockIdx.x, b = blockIdx.y, t = blockIdx.z;
    int c = threadIdx.x;
    const float* in = t ? tfeat : sfeat;
    float* dst = t ? g_ttok : g_stok;
    int k = yo >> 1; int r0, r1; float wy0, wy1;
    if (yo & 1) { r0 = k; r1 = (k < 15) ? k + 1 : 15; wy0 = 0.75f; wy1 = 0.25f; }
    else        { r0 = (k > 0) ? k - 1 : 0; r1 = k;   wy0 = 0.25f; wy1 = 0.75f; }
    const float* base = in + ((size_t)b * CF + c) * 256;
    float a0[16], a1[16];
#pragma unroll
    for (int x = 0; x < 16; x++) { a0[x] = base[r0*16 + x]; a1[x] = base[r1*16 + x]; }
#pragma unroll
    for (int xo = 0; xo < 32; xo++) {
        int kx = xo >> 1; int x0, x1; float wx0, wx1;
        if (xo & 1) { x0 = kx; x1 = (kx < 15) ? kx + 1 : 15; wx0 = 0.75f; wx1 = 0.25f; }
        else        { x0 = (kx > 0) ? kx - 1 : 0; x1 = kx;   wx0 = 0.25f; wx1 = 0.75f; }
        float v0 = wy0 * a0[x0] + wy1 * a1[x0];
        float v1 = wy0 * a0[x1] + wy1 * a1[x1];
        dst[((size_t)b * NT + yo*32 + xo) * CF + c] = wx0 * v0 + wx1 * v1;
    }
}

// merged patch stats. grid (NT/4, B, 2), block 256; z=0 source, z=1 target
__global__ void __launch_bounds__(256) k_patch(const int* __restrict__ slab,
                                               const float* __restrict__ tp) {
    int b = blockIdx.y, tid = threadIdx.x;
    int p = tid >> 6, r = tid & 63;
    int pi = r >> 2, xq = r & 3;
    int n = blockIdx.x * 4 + p;
    int y = (n >> 5) * 16 + pi;
    int xb = (n & 31) * 16 + xq * 4;
    __shared__ int h[4][20];
    if (tid < 80) h[tid / 20][tid % 20] = 0;

    if (blockIdx.z == 0) {
        const int4* s4 = (const int4*)slab;
        int4 v = s4[((size_t)b * IMG + y) * (IMG/4) + (xb >> 2)];
        __syncthreads();
        atomicAdd(&h[p][v.x + 1], 1); atomicAdd(&h[p][v.y + 1], 1);
        atomicAdd(&h[p][v.z + 1], 1); atomicAdd(&h[p][v.w + 1], 1);
        __syncthreads();
        if (r == 0) {
            int best = -1, mj = 0;
            for (int j = 0; j < 20; j++) if (h[p][j] > best) { best = h[p][j]; mj = j; }
            int mode = mj - 1;
            int nvalid = 256 - h[p][0];
            int agree = (mode >= 0) ? h[p][mj] : 0;
            float purity = (float)agree / (float)(nvalid > 0 ? nvalid : 1);
            g_mode[b * NT + n] = mode;
            g_pure[b * NT + n] = (unsigned char)((purity >= 0.9f) && (nvalid > 0));
        }
    } else {
        const float4* tp4 = (const float4*)tp;
        size_t pix4 = (((size_t)b * KC) * IMG + y) * (IMG/4) + (xb >> 2);
        float mv0=-1.f, mv1=-1.f, mv2=-1.f, mv3=-1.f;
        int mk0=0, mk1=0, mk2=0, mk3=0;
#pragma unroll
        for (int k = 0; k < KC; k++) {
            float4 v = tp4[pix4 + (size_t)k * (IMG * (IMG/4))];
            if (v.x > mv0) { mv0 = v.x; mk0 = k; }
            if (v.y > mv1) { mv1 = v.y; mk1 = k; }
            if (v.z > mv2) { mv2 = v.z; mk2 = k; }
            if (v.w > mv3) { mv3 = v.w; mk3 = k; }
        }
        __shared__ float sc[256];
        sc[tid] = mv0 + mv1 + mv2 + mv3;
        __syncthreads();
        int l0 = (mv0 < 0.9f) ? 0 : mk0 + 1;
        int l1 = (mv1 < 0.9f) ? 0 : mk1 + 1;
        int l2 = (mv2 < 0.9f) ? 0 : mk2 + 1;
        int l3 = (mv3 < 0.9f) ? 0 : mk3 + 1;
        atomicAdd(&h[p][l0], 1); atomicAdd(&h[p][l1], 1);
        atomicAdd(&h[p][l2], 1); atomicAdd(&h[p][l3], 1);
        __syncthreads();
        for (int s = 32; s > 0; s >>= 1) {
            if (r < s) sc[tid] += sc[tid + s];
            __syncthreads();
        }
        if (r == 0) {
            float cmean = sc[p * 64] / 256.f;
            int best = -1, mj = 0;
            for (int j = 0; j < 20; j++) if (h[p][j] > best) { best = h[p][j]; mj = j; }
            int mode = mj - 1;
            int nvalid = 256 - h[p][0];
            int agree = (mode >= 0) ? h[p][mj] : 0;
            float purity = (float)agree / (float)(nvalid > 0 ? nvalid : 1);
            int pure = (purity >= 0.9f) && (nvalid > 0) && (cmean >= 0.9f);
            g_mode[BB*NT + b * NT + n] = mode;
            g_pure[BB*NT + b * NT + n] = (unsigned char)pure;
        }
    }
}

// per-b: class lists, ranks, gates + impure stats fused. grid (B), 1024 thr.
__global__ void k_prepstats() {
    int b = blockIdx.x;
    int tid = threadIdx.x, w = tid >> 5, lane = tid & 31;
    __shared__ int simp[2][NT];
    __shared__ int simpcnt[2];
    for (int item = w; item < 40; item += 32) {
        if (item < TK) {
            int t = item / KC, k = item % KC;
            const int* md = g_mode + t * BB * NT + b * NT;
            const unsigned char* pu = g_pure + t * BB * NT + b * NT;
            int cnt = 0;
            for (int base = 0; base < NT; base += 32) {
                int n = base + lane;
                bool mem = pu[n] && (md[n] == k);
                unsigned m = __ballot_sync(0xffffffffu, mem);
                int pos = cnt + __popc(m & ((1u << lane) - 1u));
                if (mem) {
                    g_clist[((b*2+t)*KC + k)*NT + pos] = n;
                    g_rank[(b*2+t)*NT + n] = pos;
                }
                cnt += __popc(m);
            }
            if (lane == 0) g_ccnt[(b*2+t)*KC + k] = cnt;
        } else {
            int t = item - TK;
            const unsigned char* pu = g_pure + t * BB * NT + b * NT;
            int cnt = 0;
            for (int base = 0; base < NT; base += 32) {
                int n = base + lane;
                bool mem = !pu[n];
                unsigned m = __ballot_sync(0xffffffffu, mem);
                int pos = cnt + __popc(m & ((1u << lane) - 1u));
                if (mem) simp[t][pos] = n;
                cnt += __popc(m);
            }
            if (lane == 0) simpcnt[t] = cnt;
        }
    }
    __syncthreads();
    if (tid < 2) {
        int s = 0;
        for (int k = 0; k < KC; k++) s += g_ccnt[(b*2+tid)*KC + k];
        g_gate[b*2+tid] = (s > 0);
    }
    // fused impure-token stats (two-pass, unbiased)
    int t = tid >> 9, c = tid & 511;
    int n = simpcnt[t];
    const float* feat = (t ? g_ttok : g_stok) + (size_t)b * NT * CF;
    float s = 0.f;
    for (int i = 0; i < n; i++) s += feat[(size_t)simp[t][i] * CF + c];
    float mean = s / (float)(n > 0 ? n : 1);
    float ss = 0.f;
    for (int i = 0; i < n; i++) { float d = feat[(size_t)simp[t][i] * CF + c] - mean; ss += d * d; }
    float var = ss / (float)(n - 1 > 0 ? n - 1 : 1);
    g_statmean[(b * 2 + t) * CF + c] = mean;
    g_statstd [(b * 2 + t) * CF + c] = (n > 1) ? sqrtf(var) : 0.f;
    if (tid == 0) g_both[b] = (simpcnt[0] > 0) && (simpcnt[1] > 0);
}

// per-(b,class) means, parallel over b. grid (38, B), block 512.
__global__ void k_classmeans() {
    int bid = blockIdx.x, b = blockIdx.y;   // bid = t*KC+k
    int t = bid / KC, c = threadIdx.x;
    int cnt = g_ccnt[b*TK + bid];
    __shared__ int lst[NT];
    for (int i = c; i < cnt; i += 512) lst[i] = g_clist[(b*TK + bid)*NT + i];
    __syncthreads();
    const float* feat = (t ? g_ttok : g_stok) + (size_t)b * NT * CF;
    float acc = 0.f;
    for (int i = 0; i < cnt; i++) acc += feat[(size_t)lst[i] * CF + c];
    g_mean[((size_t)b*TK + bid)*CF + c] = acc / (float)(cnt > 0 ? cnt : 1);
}

// EMA recursion over b (4 steps, tiny). grid 38, block 512.
__global__ void k_proto() {
    int bid = blockIdx.x;                   // t*KC+k
    int t = bid / KC, c = threadIdx.x;
    float pv = 0.f;
#pragma unroll
    for (int b = 0; b < BB; b++) {
        int cnt = g_ccnt[b*TK + bid];
        int gate = t ? (g_gate[b*2] && g_gate[b*2+1]) : g_gate[b*2];
        if (gate && cnt > 0)
            pv = 0.99f * pv + 0.01f * g_mean[((size_t)b*TK + bid)*CF + c];
        g_protoB[((size_t)b*TK + bid)*CF + c] = pv;
    }
    g_proto[bid * CF + c] = pv;
}

// distances, parallel over b. grid (64, 2, B), block 512 (16 warps).
__global__ void k_dist() {
    int t = blockIdx.y, b = blockIdx.z;
    int w = threadIdx.x >> 5, lane = threadIdx.x & 31;
    int n = blockIdx.x * 16 + w;
    int mode = g_mode[t * BB * NT + b * NT + n];
    int cm = mode > 0 ? mode : 0;
    const float* f = (t ? g_ttok : g_stok) + ((size_t)b * NT + n) * CF;
    const float* p = g_protoB + ((size_t)b*TK + t*KC + cm) * CF;
    float acc = 0.f;
    for (int c = lane; c < CF; c += 32) { float d = f[c] - p[c]; acc += d * d; }
    for (int o = 16; o; o >>= 1) acc += __shfl_down_sync(0xffffffffu, acc, o);
    if (lane == 0) g_dist[(b*2 + t)*NT + n] = sqrtf(acc);
}

// stable rank by distance. grid (19, 2, B), block 256.
__global__ void k_sort() {
    int k = blockIdx.x, t = blockIdx.y, b = blockIdx.z;
    int lid = (b*2+t)*KC + k;
    int m = g_ccnt[b*TK + t*KC + k];
    __shared__ int toks[NT];
    __shared__ float ds[NT];
    for (int i = threadIdx.x; i < m; i += 256) {
        int tk = g_clist[lid * NT + i];
        toks[i] = tk; ds[i] = g_dist[(b*2+t)*NT + tk];
    }
    __syncthreads();
    for (int i = threadIdx.x; i < m; i += 256) {
        float di = ds[i]; int r = 0;
        for (int j = 0; j < m; j++) {
            float dj = ds[j];
            r += (dj < di) || (dj == di && j < i);
        }
        g_order[lid * NT + r] = toks[i];
    }
}

// cyclic source matching. grid (2, B), block 1024.
__global__ void k_match() {
    int t = blockIdx.x, b = blockIdx.y, n = threadIdx.x;
    int gate_st = g_gate[b*2] && g_gate[b*2+1];
    int mode = g_mode[t * BB * NT + b * NT + n];
    int pure = g_pure[t * BB * NT + b * NT + n];
    int cm = mode > 0 ? mode : 0;
    int cs = g_ccnt[b*TK + (1 - t) * KC + cm];
    int apply = pure && (cs > 0) && gate_st;
    int src = 0;
    if (apply) {
        int r = g_rank[(b*2 + t) * NT + n];
        src = g_order[(((b*2 + (1 - t)) * KC + cm)) * NT + (r % cs)];
    }
    g_src  [(t * BB + b) * NT + n] = src;
    g_apply[(t * BB + b) * NT + n] = (unsigned char)apply;
}

// feature correction + fused proto output. grid (NT, 2, B), block 512.
__global__ void k_featcorr(const float* __restrict__ alphas, float* __restrict__ out) {
    int n = blockIdx.x, t = blockIdx.y, b = blockIdx.z, c = threadIdx.x;
    float alpha = alphas[b];
    const float* own = (t ? g_ttok : g_stok) + (size_t)b * NT * CF;
    const float* oth = (t ? g_stok : g_ttok) + (size_t)b * NT * CF;
    float f = own[(size_t)n * CF + c];
    float r = f;
    int idx = (t * BB + b) * NT + n;
    if (g_apply[idx]) {
        r = alpha * f + (1.f - alpha) * oth[(size_t)g_src[idx] * CF + c];
    } else if (!g_pure[t * BB * NT + b * NT + n] && g_both[b]) {
        float om = g_statmean[(b * 2 + t) * CF + c];
        float os = g_statstd [(b * 2 + t) * CF + c];
        float xm = g_statmean[(b * 2 + (1 - t)) * CF + c];
        float xs = g_statstd [(b * 2 + (1 - t)) * CF + c];
        float styl = (f - om) / (os + 1e-5f) * xs + xm;
        r = alpha * f + (1.f - alpha) * styl;
    }
    out[(t ? OFF_TFC : OFF_SFC) + ((size_t)b * NT + n) * CF + c] = r;
    if (b == 0 && n < KC)
        out[OFF_SP + (size_t)(t * KC + n) * CF + c] = g_proto[(t * KC + n) * CF + c];
}

// label correction; float4 streaming stores. grid (8, K*16, B*2), block 256.
__global__ void k_labelcorr(const int* __restrict__ slab, const float* __restrict__ tp,
                            float* __restrict__ out) {
    int chunk = blockIdx.x;
    int k = blockIdx.y >> 4, pi = blockIdx.y & 15;
    int b = blockIdx.z >> 1, osel = blockIdx.z & 1;   // 0=slc, 1=tlc
    int tid = threadIdx.x;
    __shared__ float seg[16][132];                     // [pj][s], padded
    int sseg = tid >> 4, pj = tid & 15;
    for (int pass = 0; pass < 8; pass++) {
        int s = pass * 16 + sseg;
        int n = chunk * 128 + s;
        int aidx = (osel * BB + b) * NT + n;
        int apply = g_apply[aidx];
        int m = apply ? g_src[aidx] : n;
        int use_probs = (osel == 0) ? apply : !apply;
        int y = (m >> 5) * 16 + pi, x = (m & 31) * 16 + pj;
        float v;
        if (use_probs) v = tp[(((size_t)b * KC + k) * IMG + y) * IMG + x];
        else v = (slab[((size_t)b * IMG + y) * IMG + x] == k) ? 1.f : 0.f;
        seg[pj][s] = v;
    }
    __syncthreads();
    size_t obase = osel ? OFF_TLC : OFF_SLC;
#pragma unroll
    for (int it = 0; it < 2; it++) {
        int f = it * 256 + tid;                        // 0..511 float4 slots
        int pjw = f >> 5, u = f & 31;
        float4 vv = *(const float4*)&seg[pjw][4 * u];
        size_t row = (size_t)b * (KC * PPX) + k * PPX + pi * 16 + pjw;
        __stcs((float4*)(out + obase + row * NT + chunk * 128) + u, vv);
    }
}

// ---------------- launch ----------------
extern "C" void kernel_launch(void* const* d_in, const int* in_sizes, int n_in,
                              void* d_out, int out_size) {
    const float* sfeat = nullptr; const float* tfeat = nullptr;
    const int* slab = nullptr; const float* tp = nullptr; const float* alphas = nullptr;
    for (int i = 0; i < n_in; i++) {
        int sz = in_sizes[i];
        if (sz == BB*CF*16*16) { if (!sfeat) sfeat = (const float*)d_in[i]; else tfeat = (const float*)d_in[i]; }
        else if (sz == BB*IMG*IMG) slab = (const int*)d_in[i];
        else if (sz == BB*KC*IMG*IMG) tp = (const float*)d_in[i];
        else if (sz == BB) alphas = (const float*)d_in[i];
    }
    float* out = (float*)d_out;

    k_patch<<<dim3(NT/4, BB, 2), 256>>>(slab, tp);
    k_upsample<<<dim3(32, BB, 2), 512>>>(sfeat, tfeat);
    k_prepstats<<<BB, 1024>>>();
    k_classmeans<<<dim3(TK, BB), 512>>>();
    k_proto<<<TK, 512>>>();
    k_dist<<<dim3(64, 2, BB), 512>>>();
    k_sort<<<dim3(KC, 2, BB), 256>>>();
    k_match<<<dim3(2, BB), 1024>>>();
    k_featcorr<<<dim3(NT, 2, BB), 512>>>(alphas, out);
    k_labelcorr<<<dim3(8, KC * 16, BB * 2), 256>>>(slab, tp, out);
}

// round 5
// speedup vs baseline: 2.0871x; 1.1547x over previous
#include <cuda_runtime.h>
#include <cuda_bf16.h>
#include <math.h>

// ---------------- problem constants ----------------
#define BB   4
#define CF   512
#define KC   19
#define NT   1024            // tokens per image (32x32)
#define IMG  512
#define PPX  256             // patch pixels (16x16)
#define TK   (2*KC)          // 38

// output layout (floats): sfc, tfc, slc, tlc, s_proto, t_proto
#define SZ_FC    ((size_t)BB*NT*CF)
#define OFF_SFC  0ULL
#define OFF_TFC  (SZ_FC)
#define OFF_SLC  (2*SZ_FC)
#define SZ_LC    ((size_t)BB*KC*PPX*NT)
#define OFF_TLC  (OFF_SLC + SZ_LC)
#define OFF_SP   (OFF_TLC + SZ_LC)

// ---------------- device scratch (static; no allocation) ----------------
__device__ float g_stok[BB*NT*CF];                 // [b][n][c]
__device__ float g_ttok[BB*NT*CF];
__device__ int           g_mode[2*BB*NT];          // [t][b][n]
__device__ unsigned char g_pure[2*BB*NT];
__device__ int   g_clist[BB*TK*NT];                // [(b*2+t)*KC+k][i]
__device__ int   g_ccnt [BB*TK];
__device__ int   g_rank [BB*2*NT];
__device__ int   g_gate [BB*2];
__device__ float g_mean  [BB*TK*CF];               // per-b class means
__device__ int   g_order[BB*TK*NT];
__device__ int           g_src  [2*BB*NT];
__device__ unsigned char g_apply[2*BB*NT];
__device__ float g_statmean[BB*2*CF];
__device__ float g_statstd [BB*2*CF];
__device__ int   g_both[BB];

// ---------------- kernels ----------------

// bilinear 2x upsample; grid (32 yo, B, 2 tensor), block 512 = channel
__global__ void k_upsample(const float* __restrict__ sfeat, const float* __restrict__ tfeat) {
    int yo = blockIdx.x, b = blockIdx.y, t = blockIdx.z;
    int c = threadIdx.x;
    const float* in = t ? tfeat : sfeat;
    float* dst = t ? g_ttok : g_stok;
    int k = yo >> 1; int r0, r1; float wy0, wy1;
    if (yo & 1) { r0 = k; r1 = (k < 15) ? k + 1 : 15; wy0 = 0.75f; wy1 = 0.25f; }
    else        { r0 = (k > 0) ? k - 1 : 0; r1 = k;   wy0 = 0.25f; wy1 = 0.75f; }
    const float4* base = (const float4*)(in + ((size_t)b * CF + c) * 256);
    float a0[16], a1[16];
#pragma unroll
    for (int q = 0; q < 4; q++) {
        float4 v0 = base[r0*4 + q], v1 = base[r1*4 + q];
        a0[q*4+0]=v0.x; a0[q*4+1]=v0.y; a0[q*4+2]=v0.z; a0[q*4+3]=v0.w;
        a1[q*4+0]=v1.x; a1[q*4+1]=v1.y; a1[q*4+2]=v1.z; a1[q*4+3]=v1.w;
    }
#pragma unroll
    for (int xo = 0; xo < 32; xo++) {
        int kx = xo >> 1; int x0, x1; float wx0, wx1;
        if (xo & 1) { x0 = kx; x1 = (kx < 15) ? kx + 1 : 15; wx0 = 0.75f; wx1 = 0.25f; }
        else        { x0 = (kx > 0) ? kx - 1 : 0; x1 = kx;   wx0 = 0.25f; wx1 = 0.75f; }
        float v0 = wy0 * a0[x0] + wy1 * a1[x0];
        float v1 = wy0 * a0[x1] + wy1 * a1[x1];
        dst[((size_t)b * NT + yo*32 + xo) * CF + c] = wx0 * v0 + wx1 * v1;
    }
}

// merged patch stats. grid (NT/4, B, 2), block 256; z=0 source, z=1 target
__global__ void __launch_bounds__(256) k_patch(const int* __restrict__ slab,
                                               const float* __restrict__ tp) {
    int b = blockIdx.y, tid = threadIdx.x;
    int p = tid >> 6, r = tid & 63;
    int pi = r >> 2, xq = r & 3;
    int n = blockIdx.x * 4 + p;
    int y = (n >> 5) * 16 + pi;
    int xb = (n & 31) * 16 + xq * 4;
    __shared__ int h[4][20];
    if (tid < 80) h[tid / 20][tid % 20] = 0;

    if (blockIdx.z == 0) {
        const int4* s4 = (const int4*)slab;
        int4 v = s4[((size_t)b * IMG + y) * (IMG/4) + (xb >> 2)];
        __syncthreads();
        atomicAdd(&h[p][v.x + 1], 1); atomicAdd(&h[p][v.y + 1], 1);
        atomicAdd(&h[p][v.z + 1], 1); atomicAdd(&h[p][v.w + 1], 1);
        __syncthreads();
        if (r == 0) {
            int best = -1, mj = 0;
            for (int j = 0; j < 20; j++) if (h[p][j] > best) { best = h[p][j]; mj = j; }
            int mode = mj - 1;
            int nvalid = 256 - h[p][0];
            int agree = (mode >= 0) ? h[p][mj] : 0;
            float purity = (float)agree / (float)(nvalid > 0 ? nvalid : 1);
            g_mode[b * NT + n] = mode;
            g_pure[b * NT + n] = (unsigned char)((purity >= 0.9f) && (nvalid > 0));
        }
    } else {
        const float4* tp4 = (const float4*)tp;
        size_t pix4 = (((size_t)b * KC) * IMG + y) * (IMG/4) + (xb >> 2);
        float mv0=-1.f, mv1=-1.f, mv2=-1.f, mv3=-1.f;
        int mk0=0, mk1=0, mk2=0, mk3=0;
#pragma unroll
        for (int k = 0; k < KC; k++) {
            float4 v = tp4[pix4 + (size_t)k * (IMG * (IMG/4))];
            if (v.x > mv0) { mv0 = v.x; mk0 = k; }
            if (v.y > mv1) { mv1 = v.y; mk1 = k; }
            if (v.z > mv2) { mv2 = v.z; mk2 = k; }
            if (v.w > mv3) { mv3 = v.w; mk3 = k; }
        }
        __shared__ float sc[256];
        sc[tid] = mv0 + mv1 + mv2 + mv3;
        __syncthreads();
        int l0 = (mv0 < 0.9f) ? 0 : mk0 + 1;
        int l1 = (mv1 < 0.9f) ? 0 : mk1 + 1;
        int l2 = (mv2 < 0.9f) ? 0 : mk2 + 1;
        int l3 = (mv3 < 0.9f) ? 0 : mk3 + 1;
        atomicAdd(&h[p][l0], 1); atomicAdd(&h[p][l1], 1);
        atomicAdd(&h[p][l2], 1); atomicAdd(&h[p][l3], 1);
        __syncthreads();
        for (int s = 32; s > 0; s >>= 1) {
            if (r < s) sc[tid] += sc[tid + s];
            __syncthreads();
        }
        if (r == 0) {
            float cmean = sc[p * 64] / 256.f;
            int best = -1, mj = 0;
            for (int j = 0; j < 20; j++) if (h[p][j] > best) { best = h[p][j]; mj = j; }
            int mode = mj - 1;
            int nvalid = 256 - h[p][0];
            int agree = (mode >= 0) ? h[p][mj] : 0;
            float purity = (float)agree / (float)(nvalid > 0 ? nvalid : 1);
            int pure = (purity >= 0.9f) && (nvalid > 0) && (cmean >= 0.9f);
            g_mode[BB*NT + b * NT + n] = mode;
            g_pure[BB*NT + b * NT + n] = (unsigned char)pure;
        }
    }
}

// per-b: class lists, ranks, gates + impure stats fused. grid (B), 1024 thr.
__global__ void k_prepstats() {
    int b = blockIdx.x;
    int tid = threadIdx.x, w = tid >> 5, lane = tid & 31;
    __shared__ int simp[2][NT];
    __shared__ int simpcnt[2];
    for (int item = w; item < 40; item += 32) {
        if (item < TK) {
            int t = item / KC, k = item % KC;
            const int* md = g_mode + t * BB * NT + b * NT;
            const unsigned char* pu = g_pure + t * BB * NT + b * NT;
            int cnt = 0;
            for (int base = 0; base < NT; base += 32) {
                int n = base + lane;
                bool mem = pu[n] && (md[n] == k);
                unsigned m = __ballot_sync(0xffffffffu, mem);
                int pos = cnt + __popc(m & ((1u << lane) - 1u));
                if (mem) {
                    g_clist[((b*2+t)*KC + k)*NT + pos] = n;
                    g_rank[(b*2+t)*NT + n] = pos;
                }
                cnt += __popc(m);
            }
            if (lane == 0) g_ccnt[(b*2+t)*KC + k] = cnt;
        } else {
            int t = item - TK;
            const unsigned char* pu = g_pure + t * BB * NT + b * NT;
            int cnt = 0;
            for (int base = 0; base < NT; base += 32) {
                int n = base + lane;
                bool mem = !pu[n];
                unsigned m = __ballot_sync(0xffffffffu, mem);
                int pos = cnt + __popc(m & ((1u << lane) - 1u));
                if (mem) simp[t][pos] = n;
                cnt += __popc(m);
            }
            if (lane == 0) simpcnt[t] = cnt;
        }
    }
    __syncthreads();
    if (tid < 2) {
        int s = 0;
        for (int k = 0; k < KC; k++) s += g_ccnt[(b*2+tid)*KC + k];
        g_gate[b*2+tid] = (s > 0);
    }
    // fused impure-token stats (two-pass, unbiased), 4-way unrolled
    int t = tid >> 9, c = tid & 511;
    int n = simpcnt[t];
    const float* feat = (t ? g_ttok : g_stok) + (size_t)b * NT * CF;
    float s0=0.f, s1=0.f, s2=0.f, s3=0.f;
    int i = 0;
    for (; i + 3 < n; i += 4) {
        s0 += feat[(size_t)simp[t][i  ] * CF + c];
        s1 += feat[(size_t)simp[t][i+1] * CF + c];
        s2 += feat[(size_t)simp[t][i+2] * CF + c];
        s3 += feat[(size_t)simp[t][i+3] * CF + c];
    }
    float s = (s0 + s1) + (s2 + s3);
    for (; i < n; i++) s += feat[(size_t)simp[t][i] * CF + c];
    float mean = s / (float)(n > 0 ? n : 1);
    float q0=0.f, q1=0.f, q2=0.f, q3=0.f;
    i = 0;
    for (; i + 3 < n; i += 4) {
        float d0 = feat[(size_t)simp[t][i  ] * CF + c] - mean;
        float d1 = feat[(size_t)simp[t][i+1] * CF + c] - mean;
        float d2 = feat[(size_t)simp[t][i+2] * CF + c] - mean;
        float d3 = feat[(size_t)simp[t][i+3] * CF + c] - mean;
        q0 += d0*d0; q1 += d1*d1; q2 += d2*d2; q3 += d3*d3;
    }
    float ss = (q0 + q1) + (q2 + q3);
    for (; i < n; i++) { float d = feat[(size_t)simp[t][i] * CF + c] - mean; ss += d * d; }
    float var = ss / (float)(n - 1 > 0 ? n - 1 : 1);
    g_statmean[(b * 2 + t) * CF + c] = mean;
    g_statstd [(b * 2 + t) * CF + c] = (n > 1) ? sqrtf(var) : 0.f;
    if (tid == 0) g_both[b] = (simpcnt[0] > 0) && (simpcnt[1] > 0);
}

// per-(b,class) means. grid (38, B), block 512, 4-way unrolled member loop.
__global__ void k_classmeans() {
    int bid = blockIdx.x, b = blockIdx.y;   // bid = t*KC+k
    int t = bid / KC, c = threadIdx.x;
    int cnt = g_ccnt[b*TK + bid];
    __shared__ int lst[NT];
    for (int i = c; i < cnt; i += 512) lst[i] = g_clist[(b*TK + bid)*NT + i];
    __syncthreads();
    const float* feat = (t ? g_ttok : g_stok) + (size_t)b * NT * CF;
    float a0=0.f, a1=0.f, a2=0.f, a3=0.f;
    int i = 0;
    for (; i + 3 < cnt; i += 4) {
        a0 += feat[(size_t)lst[i  ] * CF + c];
        a1 += feat[(size_t)lst[i+1] * CF + c];
        a2 += feat[(size_t)lst[i+2] * CF + c];
        a3 += feat[(size_t)lst[i+3] * CF + c];
    }
    float acc = (a0 + a1) + (a2 + a3);
    for (; i < cnt; i++) acc += feat[(size_t)lst[i] * CF + c];
    g_mean[((size_t)b*TK + bid)*CF + c] = acc / (float)(cnt > 0 ? cnt : 1);
}

// fused proto recursion + member distances + stable rank. grid (19,2,B), 256 thr.
__global__ void k_distsort() {
    int k = blockIdx.x, t = blockIdx.y, b = blockIdx.z;
    int bid = t*KC + k;
    int tid = threadIdx.x, w = tid >> 5, lane = tid & 31;
    __shared__ float4 pr4[CF/4];
    __shared__ int toks[NT];
    __shared__ float ds[NT];
    // recompute protoB[b] for this class from g_mean (4-step EMA)
    {
        int c = tid, c2 = tid + 256;
        float pv0 = 0.f, pv1 = 0.f;
#pragma unroll
        for (int bb = 0; bb <= 3; bb++) {
            if (bb > b) break;
            int cnt = g_ccnt[bb*TK + bid];
            int gate = t ? (g_gate[bb*2] && g_gate[bb*2+1]) : g_gate[bb*2];
            if (gate && cnt > 0) {
                pv0 = 0.99f * pv0 + 0.01f * g_mean[((size_t)bb*TK + bid)*CF + c ];
                pv1 = 0.99f * pv1 + 0.01f * g_mean[((size_t)bb*TK + bid)*CF + c2];
            }
        }
        ((float*)pr4)[c] = pv0;
        ((float*)pr4)[c2] = pv1;
    }
    int m = g_ccnt[b*TK + bid];
    for (int i = tid; i < m; i += 256) toks[i] = g_clist[(b*TK + bid)*NT + i];
    __syncthreads();
    const float* feat = (t ? g_ttok : g_stok) + (size_t)b * NT * CF;
    for (int i = w; i < m; i += 8) {
        const float4* f4 = (const float4*)(feat + (size_t)toks[i] * CF);
        float acc = 0.f;
#pragma unroll
        for (int q = 0; q < 4; q++) {
            int e = lane + q * 32;
            float4 v = f4[e];
            float4 p = pr4[e];
            float d0 = v.x - p.x, d1 = v.y - p.y, d2 = v.z - p.z, d3 = v.w - p.w;
            acc += d0*d0 + d1*d1 + d2*d2 + d3*d3;
        }
        for (int o = 16; o; o >>= 1) acc += __shfl_down_sync(0xffffffffu, acc, o);
        if (lane == 0) ds[i] = sqrtf(acc);
    }
    __syncthreads();
    int lid = (b*2+t)*KC + k;
    for (int i = tid; i < m; i += 256) {
        float di = ds[i]; int r = 0;
        for (int j = 0; j < m; j++) {
            float dj = ds[j];
            r += (dj < di) || (dj == di && j < i);
        }
        g_order[lid * NT + r] = toks[i];
    }
}

// cyclic source matching. grid (2, B), block 1024.
__global__ void k_match() {
    int t = blockIdx.x, b = blockIdx.y, n = threadIdx.x;
    int gate_st = g_gate[b*2] && g_gate[b*2+1];
    int mode = g_mode[t * BB * NT + b * NT + n];
    int pure = g_pure[t * BB * NT + b * NT + n];
    int cm = mode > 0 ? mode : 0;
    int cs = g_ccnt[b*TK + (1 - t) * KC + cm];
    int apply = pure && (cs > 0) && gate_st;
    int src = 0;
    if (apply) {
        int r = g_rank[(b*2 + t) * NT + n];
        src = g_order[(((b*2 + (1 - t)) * KC + cm)) * NT + (r % cs)];
    }
    g_src  [(t * BB + b) * NT + n] = src;
    g_apply[(t * BB + b) * NT + n] = (unsigned char)apply;
}

// feature correction (float4) + fused proto output. grid (NT, 2, B), 128 thr.
__global__ void k_featcorr(const float* __restrict__ alphas, float* __restrict__ out) {
    int n = blockIdx.x, t = blockIdx.y, b = blockIdx.z, c4 = threadIdx.x;
    float alpha = alphas[b];
    const float4* own = (const float4*)((t ? g_ttok : g_stok) + (size_t)b * NT * CF);
    const float4* oth = (const float4*)((t ? g_stok : g_ttok) + (size_t)b * NT * CF);
    float4 f = own[(size_t)n * (CF/4) + c4];
    float4 r = f;
    int idx = (t * BB + b) * NT + n;
    if (g_apply[idx]) {
        float4 o = oth[(size_t)g_src[idx] * (CF/4) + c4];
        float be = 1.f - alpha;
        r.x = alpha*f.x + be*o.x; r.y = alpha*f.y + be*o.y;
        r.z = alpha*f.z + be*o.z; r.w = alpha*f.w + be*o.w;
    } else if (!g_pure[t * BB * NT + b * NT + n] && g_both[b]) {
        const float4* omv = (const float4*)(g_statmean + (b * 2 + t) * CF);
        const float4* osv = (const float4*)(g_statstd  + (b * 2 + t) * CF);
        const float4* xmv = (const float4*)(g_statmean + (b * 2 + (1 - t)) * CF);
        const float4* xsv = (const float4*)(g_statstd  + (b * 2 + (1 - t)) * CF);
        float4 om = omv[c4], os = osv[c4], xm = xmv[c4], xs = xsv[c4];
        float be = 1.f - alpha;
        float sx = (f.x - om.x) / (os.x + 1e-5f) * xs.x + xm.x;
        float sy = (f.y - om.y) / (os.y + 1e-5f) * xs.y + xm.y;
        float sz = (f.z - om.z) / (os.z + 1e-5f) * xs.z + xm.z;
        float sw = (f.w - om.w) / (os.w + 1e-5f) * xs.w + xm.w;
        r.x = alpha*f.x + be*sx; r.y = alpha*f.y + be*sy;
        r.z = alpha*f.z + be*sz; r.w = alpha*f.w + be*sw;
    }
    ((float4*)(out + (t ? OFF_TFC : OFF_SFC)))[((size_t)b * NT + n) * (CF/4) + c4] = r;
    // fused prototype output (recompute 4-step EMA from g_mean)
    if (b == 0 && n < KC) {
        int bid = t * KC + n;
        float4 pv = make_float4(0.f, 0.f, 0.f, 0.f);
#pragma unroll
        for (int bb = 0; bb < BB; bb++) {
            int cnt = g_ccnt[bb*TK + bid];
            int gate = t ? (g_gate[bb*2] && g_gate[bb*2+1]) : g_gate[bb*2];
            if (gate && cnt > 0) {
                float4 mv = ((const float4*)(g_mean + ((size_t)bb*TK + bid)*CF))[c4];
                pv.x = 0.99f*pv.x + 0.01f*mv.x; pv.y = 0.99f*pv.y + 0.01f*mv.y;
                pv.z = 0.99f*pv.z + 0.01f*mv.z; pv.w = 0.99f*pv.w + 0.01f*mv.w;
            }
        }
        ((float4*)(out + OFF_SP))[(size_t)bid * (CF/4) + c4] = pv;
    }
}

// label correction; float4 streaming stores. grid (8, K*16, B*2), block 256.
__global__ void k_labelcorr(const int* __restrict__ slab, const float* __restrict__ tp,
                            float* __restrict__ out) {
    int chunk = blockIdx.x;
    int k = blockIdx.y >> 4, pi = blockIdx.y & 15;
    int b = blockIdx.z >> 1, osel = blockIdx.z & 1;   // 0=slc, 1=tlc
    int tid = threadIdx.x;
    __shared__ float seg[16][132];                     // [pj][s], padded
    int sseg = tid >> 4, pj = tid & 15;
    for (int pass = 0; pass < 8; pass++) {
        int s = pass * 16 + sseg;
        int n = chunk * 128 + s;
        int aidx = (osel * BB + b) * NT + n;
        int apply = g_apply[aidx];
        int m = apply ? g_src[aidx] : n;
        int use_probs = (osel == 0) ? apply : !apply;
        int y = (m >> 5) * 16 + pi, x = (m & 31) * 16 + pj;
        float v;
        if (use_probs) v = tp[(((size_t)b * KC + k) * IMG + y) * IMG + x];
        else v = (slab[((size_t)b * IMG + y) * IMG + x] == k) ? 1.f : 0.f;
        seg[pj][s] = v;
    }
    __syncthreads();
    size_t obase = osel ? OFF_TLC : OFF_SLC;
#pragma unroll
    for (int it = 0; it < 2; it++) {
        int f = it * 256 + tid;                        // 0..511 float4 slots
        int pjw = f >> 5, u = f & 31;
        float4 vv = *(const float4*)&seg[pjw][4 * u];
        size_t row = (size_t)b * (KC * PPX) + k * PPX + pi * 16 + pjw;
        __stcs((float4*)(out + obase + row * NT + chunk * 128) + u, vv);
    }
}

// ---------------- launch ----------------
extern "C" void kernel_launch(void* const* d_in, const int* in_sizes, int n_in,
                              void* d_out, int out_size) {
    const float* sfeat = nullptr; const float* tfeat = nullptr;
    const int* slab = nullptr; const float* tp = nullptr; const float* alphas = nullptr;
    for (int i = 0; i < n_in; i++) {
        int sz = in_sizes[i];
        if (sz == BB*CF*16*16) { if (!sfeat) sfeat = (const float*)d_in[i]; else tfeat = (const float*)d_in[i]; }
        else if (sz == BB*IMG*IMG) slab = (const int*)d_in[i];
        else if (sz == BB*KC*IMG*IMG) tp = (const float*)d_in[i];
        else if (sz == BB) alphas = (const float*)d_in[i];
    }
    float* out = (float*)d_out;

    k_patch<<<dim3(NT/4, BB, 2), 256>>>(slab, tp);
    k_upsample<<<dim3(32, BB, 2), 512>>>(sfeat, tfeat);
    k_prepstats<<<BB, 1024>>>();
    k_classmeans<<<dim3(TK, BB), 512>>>();
    k_distsort<<<dim3(KC, 2, BB), 256>>>();
    k_match<<<dim3(2, BB), 1024>>>();
    k_featcorr<<<dim3(NT, 2, BB), 128>>>(alphas, out);
    k_labelcorr<<<dim3(8, KC * 16, BB * 2), 256>>>(slab, tp, out);
}